// round 3
// baseline (speedup 1.0000x reference)
#include <cuda_runtime.h>
#include <cuda_bf16.h>
#include <math.h>
#include <stdint.h>

#define EMBED   512
#define NHEAD   8
#define DHEAD   64
#define LQ      2048
#define LK      2048
#define BATCH   4
#define MROWS   (BATCH * LQ)
#define SCALE   0.125f
#define FULLMASK 0xffffffffu

// ---------------- scratch ----------------
__device__ float g_Q[MROWS * EMBED];
__device__ float g_K[MROWS * EMBED];
__device__ float g_V[MROWS * EMBED];
__device__ float g_C[MROWS * EMBED];

// ---------------- helpers ----------------
__device__ __forceinline__ float tf32r(float x) {
    uint32_t u;
    asm("cvt.rna.tf32.f32 %0, %1;" : "=r"(u) : "f"(x));
    return __uint_as_float(u);
}

__device__ __forceinline__ void mma_tf32(float4& d, const float* a, const float* b) {
    asm volatile(
        "mma.sync.aligned.m16n8k8.row.col.f32.tf32.tf32.f32 "
        "{%0,%1,%2,%3}, {%4,%5,%6,%7}, {%8,%9}, {%0,%1,%2,%3};"
        : "+f"(d.x), "+f"(d.y), "+f"(d.z), "+f"(d.w)
        : "r"(__float_as_uint(a[0])), "r"(__float_as_uint(a[1])),
          "r"(__float_as_uint(a[2])), "r"(__float_as_uint(a[3])),
          "r"(__float_as_uint(b[0])), "r"(__float_as_uint(b[1])));
}

__device__ __forceinline__ void mma_bf16(float4& d, const uint32_t* a, const uint32_t* b) {
    asm volatile(
        "mma.sync.aligned.m16n8k16.row.col.f32.bf16.bf16.f32 "
        "{%0,%1,%2,%3}, {%4,%5,%6,%7}, {%8,%9}, {%0,%1,%2,%3};"
        : "+f"(d.x), "+f"(d.y), "+f"(d.z), "+f"(d.w)
        : "r"(a[0]), "r"(a[1]), "r"(a[2]), "r"(a[3]), "r"(b[0]), "r"(b[1]));
}

__device__ __forceinline__ uint32_t pack_bf16(float x, float y) {
    __nv_bfloat162 p = __floats2bfloat162_rn(x, y);
    return *reinterpret_cast<uint32_t*>(&p);
}

// split float into bf16 hi + bf16 lo(residual)
__device__ __forceinline__ void split_bf16(float v, float& hi_f, float& lo_f) {
    __nv_bfloat16 h = __float2bfloat16_rn(v);
    hi_f = __bfloat162float(h);
    lo_f = v - hi_f;
}

// ===========================================================================
// GEMM (3x BF16 split): C[M,512] = A[M,512] @ W[512,512] + bias
// block 128x128, BK=32, 256 thr, 8 warps (2 wm x 4 wn), warp tile 64x32
// A stored as k-pair-packed uint32: Ah/Al [128][20], 16 kk + pad
// W stored as k-pair-packed uint32: Wh/Wl [16][136]
// ===========================================================================
#define GB_AST 20
#define GB_WST 136
#define GB_AH  0
#define GB_AL  (128 * GB_AST)
#define GB_WH  (2 * 128 * GB_AST)
#define GB_WL  (2 * 128 * GB_AST + 16 * GB_WST)
#define GB_SMEM_U32 (2 * 128 * GB_AST + 2 * 16 * GB_WST)

__global__ void __launch_bounds__(256, 2) gemm_bf16x3_kernel(
    const float* __restrict__ A, const float* __restrict__ W,
    const float* __restrict__ bias, float* __restrict__ C)
{
    extern __shared__ uint32_t smu[];
    uint32_t* Ah = smu + GB_AH;
    uint32_t* Al = smu + GB_AL;
    uint32_t* Wh = smu + GB_WH;
    uint32_t* Wl = smu + GB_WL;

    const int t = threadIdx.x, lane = t & 31, w = t >> 5;
    const int wm = w & 1, wn = w >> 1;
    const int lq = lane >> 2, lc = lane & 3;
    const int m0 = blockIdx.y * 128, n0 = blockIdx.x * 128;

    float4 acc[4][4];
    #pragma unroll
    for (int i = 0; i < 4; i++)
        #pragma unroll
        for (int j = 0; j < 4; j++)
            acc[i][j] = make_float4(0.f, 0.f, 0.f, 0.f);

    const int arow = t >> 1, acol0 = (t & 1) * 16;     // A: 128 rows, 2 thr/row
    const int wkk  = t >> 4, wcol0 = (t & 15) * 8;     // W: 16 kk, 16 thr each

    for (int k0 = 0; k0 < 512; k0 += 32) {
        __syncthreads();
        // ---- load & split A tile (128 x 32) ----
        #pragma unroll
        for (int j = 0; j < 4; j++) {
            float4 v = *(const float4*)(A + (size_t)(m0 + arow) * 512 + k0 + acol0 + 4 * j);
            float hx, lx, hy, ly, hz, lz, hw, lw;
            split_bf16(v.x, hx, lx); split_bf16(v.y, hy, ly);
            split_bf16(v.z, hz, lz); split_bf16(v.w, hw, lw);
            int kk = (acol0 >> 1) + 2 * j;
            uint2 uh = make_uint2(pack_bf16(hx, hy), pack_bf16(hz, hw));
            uint2 ul = make_uint2(pack_bf16(lx, ly), pack_bf16(lz, lw));
            *(uint2*)(Ah + arow * GB_AST + kk) = uh;
            *(uint2*)(Al + arow * GB_AST + kk) = ul;
        }
        // ---- load & split W tile (32 x 128), packing k-pairs ----
        #pragma unroll
        for (int j = 0; j < 2; j++) {
            int c = wcol0 + 4 * j;
            float4 va = *(const float4*)(W + (size_t)(k0 + 2 * wkk)     * 512 + n0 + c);
            float4 vb = *(const float4*)(W + (size_t)(k0 + 2 * wkk + 1) * 512 + n0 + c);
            float hax, lax, hay, lay, haz, laz, haw, law;
            float hbx, lbx, hby, lby, hbz, lbz, hbw, lbw;
            split_bf16(va.x, hax, lax); split_bf16(va.y, hay, lay);
            split_bf16(va.z, haz, laz); split_bf16(va.w, haw, law);
            split_bf16(vb.x, hbx, lbx); split_bf16(vb.y, hby, lby);
            split_bf16(vb.z, hbz, lbz); split_bf16(vb.w, hbw, lbw);
            uint4 uh = make_uint4(pack_bf16(hax, hbx), pack_bf16(hay, hby),
                                  pack_bf16(haz, hbz), pack_bf16(haw, hbw));
            uint4 ul = make_uint4(pack_bf16(lax, lbx), pack_bf16(lay, lby),
                                  pack_bf16(laz, lbz), pack_bf16(law, lbw));
            *(uint4*)(Wh + wkk * GB_WST + c) = uh;
            *(uint4*)(Wl + wkk * GB_WST + c) = ul;
        }
        __syncthreads();

        #pragma unroll
        for (int ks = 0; ks < 2; ks++) {
            // B fragments for all ni
            uint32_t bh[4][2], bl[4][2];
            #pragma unroll
            for (int ni = 0; ni < 4; ni++) {
                int n = wn * 32 + ni * 8 + lq;
                bh[ni][0] = Wh[(ks * 8 + lc) * GB_WST + n];
                bh[ni][1] = Wh[(ks * 8 + lc + 4) * GB_WST + n];
                bl[ni][0] = Wl[(ks * 8 + lc) * GB_WST + n];
                bl[ni][1] = Wl[(ks * 8 + lc + 4) * GB_WST + n];
            }
            #pragma unroll
            for (int mi = 0; mi < 4; mi++) {
                int r = wm * 64 + mi * 16 + lq;
                uint32_t ah[4], al[4];
                ah[0] = Ah[r * GB_AST + ks * 8 + lc];
                ah[1] = Ah[(r + 8) * GB_AST + ks * 8 + lc];
                ah[2] = Ah[r * GB_AST + ks * 8 + lc + 4];
                ah[3] = Ah[(r + 8) * GB_AST + ks * 8 + lc + 4];
                al[0] = Al[r * GB_AST + ks * 8 + lc];
                al[1] = Al[(r + 8) * GB_AST + ks * 8 + lc];
                al[2] = Al[r * GB_AST + ks * 8 + lc + 4];
                al[3] = Al[(r + 8) * GB_AST + ks * 8 + lc + 4];
                #pragma unroll
                for (int ni = 0; ni < 4; ni++) {
                    mma_bf16(acc[mi][ni], ah, bh[ni]);
                    mma_bf16(acc[mi][ni], ah, bl[ni]);
                    mma_bf16(acc[mi][ni], al, bh[ni]);
                }
            }
        }
    }

    #pragma unroll
    for (int mi = 0; mi < 4; mi++) {
        int r = m0 + wm * 64 + mi * 16 + lq;
        #pragma unroll
        for (int ni = 0; ni < 4; ni++) {
            int c = n0 + wn * 32 + ni * 8 + 2 * lc;
            float b0 = bias[c], b1 = bias[c + 1];
            *(float2*)(C + (size_t)r * 512 + c) =
                make_float2(acc[mi][ni].x + b0, acc[mi][ni].y + b1);
            *(float2*)(C + (size_t)(r + 8) * 512 + c) =
                make_float2(acc[mi][ni].z + b0, acc[mi][ni].w + b1);
        }
    }
}

// ===========================================================================
// Flash attention v3 (tf32 mma, S in registers):
// 64-q blocks, 128 thr, 4 warps; warp owns 16 rows x full 64-kv tile.
// Softmax + P relayout entirely in registers via quad shuffles.
// ===========================================================================
#define F_QST 68
#define F_KST 68
#define F_VST 72
#define F_QS  0
#define F_KS  (64 * F_QST)
#define F_VS  (F_KS + 64 * F_KST)
#define F_SMEM_FLOATS (F_VS + 64 * F_VST)

__global__ void __launch_bounds__(128, 3) flash_v3_kernel(
    const float* __restrict__ Q, const float* __restrict__ K,
    const float* __restrict__ V, float* __restrict__ O)
{
    extern __shared__ float sm[];
    float* Qs = sm + F_QS;
    float* Ks = sm + F_KS;
    float* Vs = sm + F_VS;

    const int t = threadIdx.x, lane = t & 31, w = t >> 5;
    const int lq = lane >> 2, lc = lane & 3;
    const int bb_ = blockIdx.z, hh = blockIdx.y;
    const int q0 = blockIdx.x * 64;

    const int ldr = t >> 1;              // 64 rows, 2 thr/row
    const int ldc0 = (t & 1) * 32;       // 32 floats per thread

    // stage Q (scaled + tf32-rounded)
    {
        const size_t base = ((size_t)bb_ * LQ + q0) * EMBED + hh * DHEAD;
        #pragma unroll
        for (int j = 0; j < 8; j++) {
            float4 v = *(const float4*)(Q + base + (size_t)ldr * EMBED + ldc0 + 4 * j);
            v.x = tf32r(v.x * SCALE); v.y = tf32r(v.y * SCALE);
            v.z = tf32r(v.z * SCALE); v.w = tf32r(v.w * SCALE);
            *(float4*)(Qs + ldr * F_QST + ldc0 + 4 * j) = v;
        }
    }
    __syncthreads();

    // hoist Q fragments to registers (constant across all KV tiles)
    float qf[8][4];
    {
        const int r0 = w * 16 + lq;
        #pragma unroll
        for (int ks = 0; ks < 8; ks++) {
            qf[ks][0] = Qs[r0 * F_QST + ks * 8 + lc];
            qf[ks][1] = Qs[(r0 + 8) * F_QST + ks * 8 + lc];
            qf[ks][2] = Qs[r0 * F_QST + ks * 8 + lc + 4];
            qf[ks][3] = Qs[(r0 + 8) * F_QST + ks * 8 + lc + 4];
        }
    }

    float mrun0 = -INFINITY, mrun1 = -INFINITY;
    float lrun0 = 0.f, lrun1 = 0.f;
    float4 o[8];
    #pragma unroll
    for (int ni = 0; ni < 8; ni++) o[ni] = make_float4(0.f, 0.f, 0.f, 0.f);

    const size_t kvbase = (size_t)bb_ * LK * EMBED + hh * DHEAD;

    for (int kt = 0; kt < LK / 64; kt++) {
        __syncthreads();   // previous tile's consumers done
        // load K,V tile (each 64x64), tf32-round
        {
            size_t g = kvbase + (size_t)(kt * 64 + ldr) * EMBED + ldc0;
            #pragma unroll
            for (int j = 0; j < 8; j++) {
                float4 kv = *(const float4*)(K + g + 4 * j);
                kv.x = tf32r(kv.x); kv.y = tf32r(kv.y);
                kv.z = tf32r(kv.z); kv.w = tf32r(kv.w);
                *(float4*)(Ks + ldr * F_KST + ldc0 + 4 * j) = kv;
            }
            #pragma unroll
            for (int j = 0; j < 8; j++) {
                float4 vv = *(const float4*)(V + g + 4 * j);
                vv.x = tf32r(vv.x); vv.y = tf32r(vv.y);
                vv.z = tf32r(vv.z); vv.w = tf32r(vv.w);
                *(float4*)(Vs + ldr * F_VST + ldc0 + 4 * j) = vv;
            }
        }
        __syncthreads();

        // ---- S = Q @ K^T : s[ni] covers kv cols ni*8..ni*8+7 ----
        float4 s[8];
        #pragma unroll
        for (int ni = 0; ni < 8; ni++) s[ni] = make_float4(0.f, 0.f, 0.f, 0.f);
        #pragma unroll
        for (int ni = 0; ni < 8; ni++) {
            const int n = ni * 8 + lq;
            #pragma unroll
            for (int ks = 0; ks < 8; ks++) {
                float b[2] = { Ks[n * F_KST + ks * 8 + lc],
                               Ks[n * F_KST + ks * 8 + lc + 4] };
                mma_tf32(s[ni], qf[ks], b);
            }
        }

        // ---- softmax in registers ----
        float mx0 = -INFINITY, mx1 = -INFINITY;
        #pragma unroll
        for (int ni = 0; ni < 8; ni++) {
            mx0 = fmaxf(mx0, fmaxf(s[ni].x, s[ni].y));
            mx1 = fmaxf(mx1, fmaxf(s[ni].z, s[ni].w));
        }
        mx0 = fmaxf(mx0, __shfl_xor_sync(FULLMASK, mx0, 1));
        mx0 = fmaxf(mx0, __shfl_xor_sync(FULLMASK, mx0, 2));
        mx1 = fmaxf(mx1, __shfl_xor_sync(FULLMASK, mx1, 1));
        mx1 = fmaxf(mx1, __shfl_xor_sync(FULLMASK, mx1, 2));

        const float mnew0 = fmaxf(mrun0, mx0);
        const float mnew1 = fmaxf(mrun1, mx1);
        const float corr0 = __expf(mrun0 - mnew0);
        const float corr1 = __expf(mrun1 - mnew1);

        float l0 = 0.f, l1 = 0.f;
        #pragma unroll
        for (int ni = 0; ni < 8; ni++) {
            s[ni].x = __expf(s[ni].x - mnew0); l0 += s[ni].x;
            s[ni].y = __expf(s[ni].y - mnew0); l0 += s[ni].y;
            s[ni].z = __expf(s[ni].z - mnew1); l1 += s[ni].z;
            s[ni].w = __expf(s[ni].w - mnew1); l1 += s[ni].w;
            s[ni].x = tf32r(s[ni].x); s[ni].y = tf32r(s[ni].y);
            s[ni].z = tf32r(s[ni].z); s[ni].w = tf32r(s[ni].w);
        }
        l0 += __shfl_xor_sync(FULLMASK, l0, 1);
        l0 += __shfl_xor_sync(FULLMASK, l0, 2);
        l1 += __shfl_xor_sync(FULLMASK, l1, 1);
        l1 += __shfl_xor_sync(FULLMASK, l1, 2);

        lrun0 = lrun0 * corr0 + l0;
        lrun1 = lrun1 * corr1 + l1;
        mrun0 = mnew0; mrun1 = mnew1;

        #pragma unroll
        for (int ni = 0; ni < 8; ni++) {
            o[ni].x *= corr0; o[ni].y *= corr0;
            o[ni].z *= corr1; o[ni].w *= corr1;
        }

        // ---- PV: O += P @ V. Relayout P frags via quad shuffles ----
        const int qbase = lane & ~3;
        #pragma unroll
        for (int kb = 0; kb < 8; kb++) {
            const int srcA = qbase + (lc >> 1);
            const int srcB = srcA + 2;
            float x0 = __shfl_sync(FULLMASK, s[kb].x, srcA);
            float y0 = __shfl_sync(FULLMASK, s[kb].y, srcA);
            float z0 = __shfl_sync(FULLMASK, s[kb].z, srcA);
            float w0 = __shfl_sync(FULLMASK, s[kb].w, srcA);
            float x1 = __shfl_sync(FULLMASK, s[kb].x, srcB);
            float y1 = __shfl_sync(FULLMASK, s[kb].y, srcB);
            float z1 = __shfl_sync(FULLMASK, s[kb].z, srcB);
            float w1 = __shfl_sync(FULLMASK, s[kb].w, srcB);
            float a[4];
            a[0] = (lc & 1) ? y0 : x0;   // P(r0, kb*8+lc)
            a[1] = (lc & 1) ? w0 : z0;   // P(r1, kb*8+lc)
            a[2] = (lc & 1) ? y1 : x1;   // P(r0, kb*8+lc+4)
            a[3] = (lc & 1) ? w1 : z1;   // P(r1, kb*8+lc+4)
            #pragma unroll
            for (int ni = 0; ni < 8; ni++) {
                float b[2] = { Vs[(kb * 8 + lc) * F_VST + ni * 8 + lq],
                               Vs[(kb * 8 + lc + 4) * F_VST + ni * 8 + lq] };
                mma_tf32(o[ni], a, b);
            }
        }
    }

    // epilogue
    const float inv0 = 1.f / lrun0;
    const float inv1 = 1.f / lrun1;
    const int r0 = w * 16 + lq;
    const size_t g0 = ((size_t)bb_ * LQ + q0 + r0) * EMBED + hh * DHEAD;
    #pragma unroll
    for (int ni = 0; ni < 8; ni++) {
        int c = ni * 8 + 2 * lc;
        *(float2*)(O + g0 + c) = make_float2(o[ni].x * inv0, o[ni].y * inv0);
        *(float2*)(O + g0 + (size_t)8 * EMBED + c) =
            make_float2(o[ni].z * inv1, o[ni].w * inv1);
    }
}

// ===========================================================================
extern "C" void kernel_launch(void* const* d_in, const int* in_sizes, int n_in,
                              void* d_out, int out_size)
{
    const float* query = (const float*)d_in[0];
    const float* key   = (const float*)d_in[1];
    const float* value = (const float*)d_in[2];
    const float* wq    = (const float*)d_in[3];
    const float* bq    = (const float*)d_in[4];
    const float* wk    = (const float*)d_in[5];
    const float* bk    = (const float*)d_in[6];
    const float* wv    = (const float*)d_in[7];
    const float* bv    = (const float*)d_in[8];
    const float* wo    = (const float*)d_in[9];
    const float* bo    = (const float*)d_in[10];
    float* out = (float*)d_out;

    float *Qp, *Kp, *Vp, *Cp;
    cudaGetSymbolAddress((void**)&Qp, g_Q);
    cudaGetSymbolAddress((void**)&Kp, g_K);
    cudaGetSymbolAddress((void**)&Vp, g_V);
    cudaGetSymbolAddress((void**)&Cp, g_C);

    const size_t gemm_smem  = (size_t)GB_SMEM_U32 * sizeof(uint32_t);   // ~37.9 KB
    const size_t flash_smem = (size_t)F_SMEM_FLOATS * sizeof(float);    // ~53.2 KB
    cudaFuncSetAttribute(gemm_bf16x3_kernel,
                         cudaFuncAttributeMaxDynamicSharedMemorySize, (int)gemm_smem);
    cudaFuncSetAttribute(flash_v3_kernel,
                         cudaFuncAttributeMaxDynamicSharedMemorySize, (int)flash_smem);

    dim3 gGemm(EMBED / 128, MROWS / 128);   // (4, 64)

    gemm_bf16x3_kernel<<<gGemm, 256, gemm_smem>>>(query, wq, bq, Qp);
    gemm_bf16x3_kernel<<<gGemm, 256, gemm_smem>>>(key,   wk, bk, Kp);
    gemm_bf16x3_kernel<<<gGemm, 256, gemm_smem>>>(value, wv, bv, Vp);

    flash_v3_kernel<<<dim3(LQ / 64, NHEAD, BATCH), 128, flash_smem>>>(Qp, Kp, Vp, Cp);

    gemm_bf16x3_kernel<<<gGemm, 256, gemm_smem>>>(Cp, wo, bo, out);
}

// round 5
// speedup vs baseline: 1.1441x; 1.1441x over previous
#include <cuda_runtime.h>
#include <cuda_bf16.h>
#include <math.h>
#include <stdint.h>

#define EMBED   512
#define NHEAD   8
#define DHEAD   64
#define LQ      2048
#define LK      2048
#define BATCH   4
#define MROWS   (BATCH * LQ)
#define SCALE   0.125f
#define FULLMASK 0xffffffffu

// ---------------- scratch ----------------
__device__ float g_Q[MROWS * EMBED];
__device__ float g_K[MROWS * EMBED];
__device__ float g_V[MROWS * EMBED];
__device__ float g_C[MROWS * EMBED];

// ---------------- helpers ----------------
__device__ __forceinline__ float tf32r(float x) {
    uint32_t u;
    asm("cvt.rna.tf32.f32 %0, %1;" : "=r"(u) : "f"(x));
    return __uint_as_float(u);
}

__device__ __forceinline__ void ldmx4(uint32_t r[4], uint32_t saddr) {
    asm volatile("ldmatrix.sync.aligned.m8n8.x4.shared.b16 {%0,%1,%2,%3}, [%4];"
                 : "=r"(r[0]), "=r"(r[1]), "=r"(r[2]), "=r"(r[3]) : "r"(saddr));
}

__device__ __forceinline__ void mma_tf32u(float4& d, const uint32_t* a, const uint32_t* b) {
    asm volatile(
        "mma.sync.aligned.m16n8k8.row.col.f32.tf32.tf32.f32 "
        "{%0,%1,%2,%3}, {%4,%5,%6,%7}, {%8,%9}, {%0,%1,%2,%3};"
        : "+f"(d.x), "+f"(d.y), "+f"(d.z), "+f"(d.w)
        : "r"(a[0]), "r"(a[1]), "r"(a[2]), "r"(a[3]), "r"(b[0]), "r"(b[1]));
}

__device__ __forceinline__ void mma_bf16(float4& d, const uint32_t* a, const uint32_t* b) {
    asm volatile(
        "mma.sync.aligned.m16n8k16.row.col.f32.bf16.bf16.f32 "
        "{%0,%1,%2,%3}, {%4,%5,%6,%7}, {%8,%9}, {%0,%1,%2,%3};"
        : "+f"(d.x), "+f"(d.y), "+f"(d.z), "+f"(d.w)
        : "r"(a[0]), "r"(a[1]), "r"(a[2]), "r"(a[3]), "r"(b[0]), "r"(b[1]));
}

__device__ __forceinline__ uint32_t pack_bf16(float x, float y) {
    __nv_bfloat162 p = __floats2bfloat162_rn(x, y);
    return *reinterpret_cast<uint32_t*>(&p);
}

__device__ __forceinline__ void split_bf16(float v, float& hi_f, float& lo_f) {
    __nv_bfloat16 h = __float2bfloat16_rn(v);
    hi_f = __bfloat162float(h);
    lo_f = v - hi_f;
}

// ===========================================================================
// GEMM (3x BF16 split) with ldmatrix A-fragments.
// block 128x128, BK=32, 256 thr, 8 warps (2 wm x 4 wn), warp tile 64x32
// ===========================================================================
#define GB_AST 20
#define GB_WST 136
#define GB_AH  0
#define GB_AL  (128 * GB_AST)
#define GB_WH  (2 * 128 * GB_AST)
#define GB_WL  (2 * 128 * GB_AST + 16 * GB_WST)
#define GB_SMEM_U32 (2 * 128 * GB_AST + 2 * 16 * GB_WST)

__global__ void __launch_bounds__(256, 2) gemm_bf16x3_kernel(
    const float* __restrict__ A, const float* __restrict__ W,
    const float* __restrict__ bias, float* __restrict__ C)
{
    extern __shared__ uint32_t smu[];
    uint32_t* Ah = smu + GB_AH;
    uint32_t* Al = smu + GB_AL;
    uint32_t* Wh = smu + GB_WH;
    uint32_t* Wl = smu + GB_WL;

    const int t = threadIdx.x, lane = t & 31, w = t >> 5;
    const int wm = w & 1, wn = w >> 1;
    const int lq = lane >> 2, lc = lane & 3;
    const int m0 = blockIdx.y * 128, n0 = blockIdx.x * 128;

    const uint32_t sbase = (uint32_t)__cvta_generic_to_shared(smu);

    uint32_t ahp[4], alp[4];
    #pragma unroll
    for (int mi = 0; mi < 4; mi++) {
        int r = wm * 64 + mi * 16 + (lane & 15);
        ahp[mi] = sbase + 4 * (GB_AH + r * GB_AST) + (lane & 16);
        alp[mi] = sbase + 4 * (GB_AL + r * GB_AST) + (lane & 16);
    }

    float4 acc[4][4];
    #pragma unroll
    for (int i = 0; i < 4; i++)
        #pragma unroll
        for (int j = 0; j < 4; j++)
            acc[i][j] = make_float4(0.f, 0.f, 0.f, 0.f);

    const int arow = t >> 1, acol0 = (t & 1) * 16;
    const int wkk  = t >> 4, wcol0 = (t & 15) * 8;

    for (int k0 = 0; k0 < 512; k0 += 32) {
        __syncthreads();
        // ---- load & split A tile (128 x 32) ----
        #pragma unroll
        for (int j = 0; j < 4; j++) {
            float4 v = *(const float4*)(A + (size_t)(m0 + arow) * 512 + k0 + acol0 + 4 * j);
            float hx, lx, hy, ly, hz, lz, hw, lw;
            split_bf16(v.x, hx, lx); split_bf16(v.y, hy, ly);
            split_bf16(v.z, hz, lz); split_bf16(v.w, hw, lw);
            int kk = (acol0 >> 1) + 2 * j;
            *(uint2*)(Ah + arow * GB_AST + kk) = make_uint2(pack_bf16(hx, hy), pack_bf16(hz, hw));
            *(uint2*)(Al + arow * GB_AST + kk) = make_uint2(pack_bf16(lx, ly), pack_bf16(lz, lw));
        }
        // ---- load & split W tile (32 x 128), packing k-pairs ----
        #pragma unroll
        for (int j = 0; j < 2; j++) {
            int c = wcol0 + 4 * j;
            float4 va = *(const float4*)(W + (size_t)(k0 + 2 * wkk)     * 512 + n0 + c);
            float4 vb = *(const float4*)(W + (size_t)(k0 + 2 * wkk + 1) * 512 + n0 + c);
            float hax, lax, hay, lay, haz, laz, haw, law;
            float hbx, lbx, hby, lby, hbz, lbz, hbw, lbw;
            split_bf16(va.x, hax, lax); split_bf16(va.y, hay, lay);
            split_bf16(va.z, haz, laz); split_bf16(va.w, haw, law);
            split_bf16(vb.x, hbx, lbx); split_bf16(vb.y, hby, lby);
            split_bf16(vb.z, hbz, lbz); split_bf16(vb.w, hbw, lbw);
            *(uint4*)(Wh + wkk * GB_WST + c) =
                make_uint4(pack_bf16(hax, hbx), pack_bf16(hay, hby),
                           pack_bf16(haz, hbz), pack_bf16(haw, hbw));
            *(uint4*)(Wl + wkk * GB_WST + c) =
                make_uint4(pack_bf16(lax, lbx), pack_bf16(lay, lby),
                           pack_bf16(laz, lbz), pack_bf16(law, lbw));
        }
        __syncthreads();

        #pragma unroll
        for (int ks = 0; ks < 2; ks++) {
            uint32_t bh[4][2], bl[4][2];
            #pragma unroll
            for (int ni = 0; ni < 4; ni++) {
                int n = wn * 32 + ni * 8 + lq;
                bh[ni][0] = Wh[(ks * 8 + lc) * GB_WST + n];
                bh[ni][1] = Wh[(ks * 8 + lc + 4) * GB_WST + n];
                bl[ni][0] = Wl[(ks * 8 + lc) * GB_WST + n];
                bl[ni][1] = Wl[(ks * 8 + lc + 4) * GB_WST + n];
            }
            #pragma unroll
            for (int mi = 0; mi < 4; mi++) {
                uint32_t ah[4], al[4];
                ldmx4(ah, ahp[mi] + ks * 32);
                ldmx4(al, alp[mi] + ks * 32);
                #pragma unroll
                for (int ni = 0; ni < 4; ni++) {
                    mma_bf16(acc[mi][ni], ah, bh[ni]);
                    mma_bf16(acc[mi][ni], ah, bl[ni]);
                    mma_bf16(acc[mi][ni], al, bh[ni]);
                }
            }
        }
    }

    #pragma unroll
    for (int mi = 0; mi < 4; mi++) {
        int r = m0 + wm * 64 + mi * 16 + lq;
        #pragma unroll
        for (int ni = 0; ni < 4; ni++) {
            int c = n0 + wn * 32 + ni * 8 + 2 * lc;
            float b0 = bias[c], b1 = bias[c + 1];
            *(float2*)(C + (size_t)r * 512 + c) =
                make_float2(acc[mi][ni].x + b0, acc[mi][ni].y + b1);
            *(float2*)(C + (size_t)(r + 8) * 512 + c) =
                make_float2(acc[mi][ni].z + b0, acc[mi][ni].w + b1);
        }
    }
}

// ===========================================================================
// Flash attention v5 (tf32 mma + ldmatrix fragments)
// 128-q blocks, 256 thr, 8 warps (4 wm x 2 wn), warp tile 32x32.
// ===========================================================================
#define F_QST 68
#define F_KST 68
#define F_VST 72
#define F_SST 68
#define F_QS  0
#define F_KS  (128 * F_QST)
#define F_VS  (F_KS + 64 * F_KST)
#define F_SS  (F_VS + 64 * F_VST)
#define F_MS  (F_SS + 128 * F_SST)
#define F_LS  (F_MS + 128)
#define F_CS  (F_LS + 128)
#define F_SMEM_FLOATS (F_CS + 128)

__global__ void __launch_bounds__(256, 2) flash_v5_kernel(
    const float* __restrict__ Q, const float* __restrict__ K,
    const float* __restrict__ V, float* __restrict__ O)
{
    extern __shared__ float sm[];
    float* Qs = sm + F_QS;
    float* Ks = sm + F_KS;
    float* Vs = sm + F_VS;
    float* Ss = sm + F_SS;
    float* Ms = sm + F_MS;
    float* Ls = sm + F_LS;
    float* Cs = sm + F_CS;

    const int t = threadIdx.x, lane = t & 31, w = t >> 5;
    const int wm = w & 3, wn = w >> 2;
    const int lq = lane >> 2, lc = lane & 3;
    const int bb_ = blockIdx.z, hh = blockIdx.y;
    const int q0 = blockIdx.x * 128;

    const uint32_t sbase = (uint32_t)__cvta_generic_to_shared(sm);

    // ldmatrix pointers
    uint32_t qap[2], pap[2], kbp[4];
    #pragma unroll
    for (int mi = 0; mi < 2; mi++) {
        int r = wm * 32 + mi * 16 + (lane & 15);
        qap[mi] = sbase + 4 * (F_QS + r * F_QST) + (lane & 16);
        pap[mi] = sbase + 4 * (F_SS + r * F_SST) + (lane & 16);
    }
    #pragma unroll
    for (int ni = 0; ni < 4; ni++) {
        int r = wn * 32 + ni * 8 + (lane & 7);
        kbp[ni] = sbase + 4 * (F_KS + r * F_KST) + ((lane >> 3) & 3) * 16;
    }

    const int lr = t >> 4, lcol = (t & 15) * 4;   // Q loader (128 rows, 16 thr/row)
    const int ldr = t >> 2, ldc0 = (t & 3) * 16;  // K/V loader (64 rows, 4 thr/row)

    // stage Q (scaled + tf32-rounded)
    {
        const size_t base = ((size_t)bb_ * LQ + q0) * EMBED + hh * DHEAD;
        #pragma unroll
        for (int p = 0; p < 8; p++) {
            int r = p * 16 + lr;
            float4 v = *(const float4*)(Q + base + (size_t)r * EMBED + lcol);
            v.x = tf32r(v.x * SCALE); v.y = tf32r(v.y * SCALE);
            v.z = tf32r(v.z * SCALE); v.w = tf32r(v.w * SCALE);
            *(float4*)(Qs + r * F_QST + lcol) = v;
        }
    }
    if (t < 128) { Ms[t] = -INFINITY; Ls[t] = 0.f; }

    float4 o[2][4];
    #pragma unroll
    for (int i = 0; i < 2; i++)
        #pragma unroll
        for (int j = 0; j < 4; j++)
            o[i][j] = make_float4(0.f, 0.f, 0.f, 0.f);

    const size_t kvbase = (size_t)bb_ * LK * EMBED + hh * DHEAD;

    for (int kt = 0; kt < LK / 64; kt++) {
        __syncthreads();
        // load K,V tile (64x64 each), tf32-round; 4 threads per row
        {
            size_t g = kvbase + (size_t)(kt * 64 + ldr) * EMBED + ldc0;
            #pragma unroll
            for (int j = 0; j < 4; j++) {
                float4 kv = *(const float4*)(K + g + 4 * j);
                kv.x = tf32r(kv.x); kv.y = tf32r(kv.y);
                kv.z = tf32r(kv.z); kv.w = tf32r(kv.w);
                *(float4*)(Ks + ldr * F_KST + ldc0 + 4 * j) = kv;
            }
            #pragma unroll
            for (int j = 0; j < 4; j++) {
                float4 vv = *(const float4*)(V + g + 4 * j);
                vv.x = tf32r(vv.x); vv.y = tf32r(vv.y);
                vv.z = tf32r(vv.z); vv.w = tf32r(vv.w);
                *(float4*)(Vs + ldr * F_VST + ldc0 + 4 * j) = vv;
            }
        }
        __syncthreads();

        // ---- S = Q @ K^T (ldmatrix fragments) ----
        float4 s[2][4];
        #pragma unroll
        for (int i = 0; i < 2; i++)
            #pragma unroll
            for (int j = 0; j < 4; j++)
                s[i][j] = make_float4(0.f, 0.f, 0.f, 0.f);

        #pragma unroll
        for (int kp = 0; kp < 4; kp++) {
            uint32_t bfr[4][4];
            #pragma unroll
            for (int ni = 0; ni < 4; ni++)
                ldmx4(bfr[ni], kbp[ni] + kp * 64);
            #pragma unroll
            for (int mi = 0; mi < 2; mi++) {
                uint32_t a0[4], a1[4];
                ldmx4(a0, qap[mi] + kp * 64);
                ldmx4(a1, qap[mi] + kp * 64 + 32);
                #pragma unroll
                for (int ni = 0; ni < 4; ni++) {
                    mma_tf32u(s[mi][ni], a0, &bfr[ni][0]);
                    mma_tf32u(s[mi][ni], a1, &bfr[ni][2]);
                }
            }
        }

        // write S frags to smem
        #pragma unroll
        for (int mi = 0; mi < 2; mi++) {
            int r = wm * 32 + mi * 16 + lq;
            #pragma unroll
            for (int ni = 0; ni < 4; ni++) {
                int c = wn * 32 + ni * 8 + 2 * lc;
                *(float2*)(Ss + r * F_SST + c)       = make_float2(s[mi][ni].x, s[mi][ni].y);
                *(float2*)(Ss + (r + 8) * F_SST + c) = make_float2(s[mi][ni].z, s[mi][ni].w);
            }
        }
        __syncthreads();

        // ---- online softmax: 2 threads per row ----
        {
            int row = t >> 1, c0 = (t & 1) * 32;
            float* srow = Ss + row * F_SST + c0;
            float4 vb[8];
            float mloc = -INFINITY;
            #pragma unroll
            for (int j = 0; j < 8; j++) {
                vb[j] = *(float4*)(srow + 4 * j);
                mloc = fmaxf(mloc, fmaxf(fmaxf(vb[j].x, vb[j].y), fmaxf(vb[j].z, vb[j].w)));
            }
            mloc = fmaxf(mloc, __shfl_xor_sync(FULLMASK, mloc, 1));
            float mold = Ms[row];
            float mnew = fmaxf(mold, mloc);
            float corr = __expf(mold - mnew);
            float ps = 0.f;
            #pragma unroll
            for (int j = 0; j < 8; j++) {
                float4 v = vb[j];
                v.x = __expf(v.x - mnew); ps += v.x;
                v.y = __expf(v.y - mnew); ps += v.y;
                v.z = __expf(v.z - mnew); ps += v.z;
                v.w = __expf(v.w - mnew); ps += v.w;
                v.x = tf32r(v.x); v.y = tf32r(v.y);
                v.z = tf32r(v.z); v.w = tf32r(v.w);
                *(float4*)(srow + 4 * j) = v;
            }
            ps += __shfl_xor_sync(FULLMASK, ps, 1);
            if ((t & 1) == 0) {
                Ms[row] = mnew;
                Ls[row] = Ls[row] * corr + ps;
                Cs[row] = corr;
            }
        }
        __syncthreads();

        // ---- rescale O, then O += P @ V ----
        #pragma unroll
        for (int mi = 0; mi < 2; mi++) {
            int r = wm * 32 + mi * 16 + lq;
            float c1 = Cs[r], c2 = Cs[r + 8];
            #pragma unroll
            for (int ni = 0; ni < 4; ni++) {
                o[mi][ni].x *= c1; o[mi][ni].y *= c1;
                o[mi][ni].z *= c2; o[mi][ni].w *= c2;
            }
        }
        #pragma unroll
        for (int kp = 0; kp < 4; kp++) {
            uint32_t ap[2][2][4];
            #pragma unroll
            for (int mi = 0; mi < 2; mi++) {
                ldmx4(ap[mi][0], pap[mi] + kp * 64);
                ldmx4(ap[mi][1], pap[mi] + kp * 64 + 32);
            }
            #pragma unroll
            for (int half = 0; half < 2; half++) {
                const int kb = kp * 2 + half;
                #pragma unroll
                for (int ni = 0; ni < 4; ni++) {
                    int n = wn * 32 + ni * 8 + lq;
                    uint32_t b[2] = {
                        __float_as_uint(Vs[(kb * 8 + lc) * F_VST + n]),
                        __float_as_uint(Vs[(kb * 8 + lc + 4) * F_VST + n])
                    };
                    #pragma unroll
                    for (int mi = 0; mi < 2; mi++)
                        mma_tf32u(o[mi][ni], ap[mi][half], b);
                }
            }
        }
    }

    __syncthreads();
    // epilogue: normalize, write merged-head ctx
    #pragma unroll
    for (int mi = 0; mi < 2; mi++) {
        int r = wm * 32 + mi * 16 + lq;
        float inv0 = 1.f / Ls[r];
        float inv1 = 1.f / Ls[r + 8];
        size_t g0 = ((size_t)bb_ * LQ + q0 + r) * EMBED + hh * DHEAD;
        #pragma unroll
        for (int ni = 0; ni < 4; ni++) {
            int c = wn * 32 + ni * 8 + 2 * lc;
            *(float2*)(O + g0 + c) =
                make_float2(o[mi][ni].x * inv0, o[mi][ni].y * inv0);
            *(float2*)(O + g0 + (size_t)8 * EMBED + c) =
                make_float2(o[mi][ni].z * inv1, o[mi][ni].w * inv1);
        }
    }
}

// ===========================================================================
extern "C" void kernel_launch(void* const* d_in, const int* in_sizes, int n_in,
                              void* d_out, int out_size)
{
    const float* query = (const float*)d_in[0];
    const float* key   = (const float*)d_in[1];
    const float* value = (const float*)d_in[2];
    const float* wq    = (const float*)d_in[3];
    const float* bq    = (const float*)d_in[4];
    const float* wk    = (const float*)d_in[5];
    const float* bk    = (const float*)d_in[6];
    const float* wv    = (const float*)d_in[7];
    const float* bv    = (const float*)d_in[8];
    const float* wo    = (const float*)d_in[9];
    const float* bo    = (const float*)d_in[10];
    float* out = (float*)d_out;

    float *Qp, *Kp, *Vp, *Cp;
    cudaGetSymbolAddress((void**)&Qp, g_Q);
    cudaGetSymbolAddress((void**)&Kp, g_K);
    cudaGetSymbolAddress((void**)&Vp, g_V);
    cudaGetSymbolAddress((void**)&Cp, g_C);

    const size_t gemm_smem  = (size_t)GB_SMEM_U32 * sizeof(uint32_t);
    const size_t flash_smem = (size_t)F_SMEM_FLOATS * sizeof(float);   // ~107 KB
    cudaFuncSetAttribute(gemm_bf16x3_kernel,
                         cudaFuncAttributeMaxDynamicSharedMemorySize, (int)gemm_smem);
    cudaFuncSetAttribute(flash_v5_kernel,
                         cudaFuncAttributeMaxDynamicSharedMemorySize, (int)flash_smem);

    dim3 gGemm(EMBED / 128, MROWS / 128);   // (4, 64)

    gemm_bf16x3_kernel<<<gGemm, 256, gemm_smem>>>(query, wq, bq, Qp);
    gemm_bf16x3_kernel<<<gGemm, 256, gemm_smem>>>(key,   wk, bk, Kp);
    gemm_bf16x3_kernel<<<gGemm, 256, gemm_smem>>>(value, wv, bv, Vp);

    flash_v5_kernel<<<dim3(LQ / 128, NHEAD, BATCH), 256, flash_smem>>>(Qp, Kp, Vp, Cp);

    gemm_bf16x3_kernel<<<gGemm, 256, gemm_smem>>>(Cp, wo, bo, out);
}

// round 7
// speedup vs baseline: 1.1998x; 1.0487x over previous
#include <cuda_runtime.h>
#include <cuda_bf16.h>
#include <math.h>
#include <stdint.h>

#define EMBED   512
#define NHEAD   8
#define DHEAD   64
#define LQ      2048
#define LK      2048
#define BATCH   4
#define MROWS   (BATCH * LQ)
#define SCALE   0.125f
#define LOG2E   1.4426950408889634f
#define FULLMASK 0xffffffffu

// ---------------- scratch ----------------
__device__ float g_Q[MROWS * EMBED];
__device__ float g_K[MROWS * EMBED];
__device__ float g_V[MROWS * EMBED];
__device__ float g_C[MROWS * EMBED];

// ---------------- helpers ----------------
__device__ __forceinline__ float tf32r(float x) {
    uint32_t u;
    asm("cvt.rna.tf32.f32 %0, %1;" : "=r"(u) : "f"(x));
    return __uint_as_float(u);
}

__device__ __forceinline__ void ldmx4(uint32_t r[4], uint32_t saddr) {
    asm volatile("ldmatrix.sync.aligned.m8n8.x4.shared.b16 {%0,%1,%2,%3}, [%4];"
                 : "=r"(r[0]), "=r"(r[1]), "=r"(r[2]), "=r"(r[3]) : "r"(saddr));
}

__device__ __forceinline__ void mma_tf32(float4& d, const float* a, const float* b) {
    asm volatile(
        "mma.sync.aligned.m16n8k8.row.col.f32.tf32.tf32.f32 "
        "{%0,%1,%2,%3}, {%4,%5,%6,%7}, {%8,%9}, {%0,%1,%2,%3};"
        : "+f"(d.x), "+f"(d.y), "+f"(d.z), "+f"(d.w)
        : "r"(__float_as_uint(a[0])), "r"(__float_as_uint(a[1])),
          "r"(__float_as_uint(a[2])), "r"(__float_as_uint(a[3])),
          "r"(__float_as_uint(b[0])), "r"(__float_as_uint(b[1])));
}

__device__ __forceinline__ void mma_bf16(float4& d, const uint32_t* a, const uint32_t* b) {
    asm volatile(
        "mma.sync.aligned.m16n8k16.row.col.f32.bf16.bf16.f32 "
        "{%0,%1,%2,%3}, {%4,%5,%6,%7}, {%8,%9}, {%0,%1,%2,%3};"
        : "+f"(d.x), "+f"(d.y), "+f"(d.z), "+f"(d.w)
        : "r"(a[0]), "r"(a[1]), "r"(a[2]), "r"(a[3]), "r"(b[0]), "r"(b[1]));
}

__device__ __forceinline__ uint32_t pack_bf16(float x, float y) {
    __nv_bfloat162 p = __floats2bfloat162_rn(x, y);
    return *reinterpret_cast<uint32_t*>(&p);
}

__device__ __forceinline__ void split_bf16(float v, float& hi_f, float& lo_f) {
    __nv_bfloat16 h = __float2bfloat16_rn(v);
    hi_f = __bfloat162float(h);
    lo_f = v - hi_f;
}

// ===========================================================================
// GEMM (3x BF16 split) with ldmatrix A-fragments (R5, measured ~226us total).
// ===========================================================================
#define GB_AST 20
#define GB_WST 136
#define GB_AH  0
#define GB_AL  (128 * GB_AST)
#define GB_WH  (2 * 128 * GB_AST)
#define GB_WL  (2 * 128 * GB_AST + 16 * GB_WST)
#define GB_SMEM_U32 (2 * 128 * GB_AST + 2 * 16 * GB_WST)

__global__ void __launch_bounds__(256, 2) gemm_bf16x3_kernel(
    const float* __restrict__ A, const float* __restrict__ W,
    const float* __restrict__ bias, float* __restrict__ C)
{
    extern __shared__ uint32_t smu[];
    uint32_t* Ah = smu + GB_AH;
    uint32_t* Al = smu + GB_AL;
    uint32_t* Wh = smu + GB_WH;
    uint32_t* Wl = smu + GB_WL;

    const int t = threadIdx.x, lane = t & 31, w = t >> 5;
    const int wm = w & 1, wn = w >> 1;
    const int lq = lane >> 2, lc = lane & 3;
    const int m0 = blockIdx.y * 128, n0 = blockIdx.x * 128;

    const uint32_t sbase = (uint32_t)__cvta_generic_to_shared(smu);

    uint32_t ahp[4], alp[4];
    #pragma unroll
    for (int mi = 0; mi < 4; mi++) {
        int r = wm * 64 + mi * 16 + (lane & 15);
        ahp[mi] = sbase + 4 * (GB_AH + r * GB_AST) + (lane & 16);
        alp[mi] = sbase + 4 * (GB_AL + r * GB_AST) + (lane & 16);
    }

    float4 acc[4][4];
    #pragma unroll
    for (int i = 0; i < 4; i++)
        #pragma unroll
        for (int j = 0; j < 4; j++)
            acc[i][j] = make_float4(0.f, 0.f, 0.f, 0.f);

    const int arow = t >> 1, acol0 = (t & 1) * 16;
    const int wkk  = t >> 4, wcol0 = (t & 15) * 8;

    for (int k0 = 0; k0 < 512; k0 += 32) {
        __syncthreads();
        #pragma unroll
        for (int j = 0; j < 4; j++) {
            float4 v = *(const float4*)(A + (size_t)(m0 + arow) * 512 + k0 + acol0 + 4 * j);
            float hx, lx, hy, ly, hz, lz, hw, lw;
            split_bf16(v.x, hx, lx); split_bf16(v.y, hy, ly);
            split_bf16(v.z, hz, lz); split_bf16(v.w, hw, lw);
            int kk = (acol0 >> 1) + 2 * j;
            *(uint2*)(Ah + arow * GB_AST + kk) = make_uint2(pack_bf16(hx, hy), pack_bf16(hz, hw));
            *(uint2*)(Al + arow * GB_AST + kk) = make_uint2(pack_bf16(lx, ly), pack_bf16(lz, lw));
        }
        #pragma unroll
        for (int j = 0; j < 2; j++) {
            int c = wcol0 + 4 * j;
            float4 va = *(const float4*)(W + (size_t)(k0 + 2 * wkk)     * 512 + n0 + c);
            float4 vb = *(const float4*)(W + (size_t)(k0 + 2 * wkk + 1) * 512 + n0 + c);
            float hax, lax, hay, lay, haz, laz, haw, law;
            float hbx, lbx, hby, lby, hbz, lbz, hbw, lbw;
            split_bf16(va.x, hax, lax); split_bf16(va.y, hay, lay);
            split_bf16(va.z, haz, laz); split_bf16(va.w, haw, law);
            split_bf16(vb.x, hbx, lbx); split_bf16(vb.y, hby, lby);
            split_bf16(vb.z, hbz, lbz); split_bf16(vb.w, hbw, lbw);
            *(uint4*)(Wh + wkk * GB_WST + c) =
                make_uint4(pack_bf16(hax, hbx), pack_bf16(hay, hby),
                           pack_bf16(haz, hbz), pack_bf16(haw, hbw));
            *(uint4*)(Wl + wkk * GB_WST + c) =
                make_uint4(pack_bf16(lax, lbx), pack_bf16(lay, lby),
                           pack_bf16(laz, lbz), pack_bf16(law, lbw));
        }
        __syncthreads();

        #pragma unroll
        for (int ks = 0; ks < 2; ks++) {
            uint32_t bh[4][2], bl[4][2];
            #pragma unroll
            for (int ni = 0; ni < 4; ni++) {
                int n = wn * 32 + ni * 8 + lq;
                bh[ni][0] = Wh[(ks * 8 + lc) * GB_WST + n];
                bh[ni][1] = Wh[(ks * 8 + lc + 4) * GB_WST + n];
                bl[ni][0] = Wl[(ks * 8 + lc) * GB_WST + n];
                bl[ni][1] = Wl[(ks * 8 + lc + 4) * GB_WST + n];
            }
            #pragma unroll
            for (int mi = 0; mi < 4; mi++) {
                uint32_t ah[4], al[4];
                ldmx4(ah, ahp[mi] + ks * 32);
                ldmx4(al, alp[mi] + ks * 32);
                #pragma unroll
                for (int ni = 0; ni < 4; ni++) {
                    mma_bf16(acc[mi][ni], ah, bh[ni]);
                    mma_bf16(acc[mi][ni], ah, bl[ni]);
                    mma_bf16(acc[mi][ni], al, bh[ni]);
                }
            }
        }
    }

    #pragma unroll
    for (int mi = 0; mi < 4; mi++) {
        int r = m0 + wm * 64 + mi * 16 + lq;
        #pragma unroll
        for (int ni = 0; ni < 4; ni++) {
            int c = n0 + wn * 32 + ni * 8 + 2 * lc;
            float b0 = bias[c], b1 = bias[c + 1];
            *(float2*)(C + (size_t)r * 512 + c) =
                make_float2(acc[mi][ni].x + b0, acc[mi][ni].y + b1);
            *(float2*)(C + (size_t)(r + 8) * 512 + c) =
                make_float2(acc[mi][ni].z + b0, acc[mi][ni].w + b1);
        }
    }
}

// ===========================================================================
// Flash attention v7: R2 geometry (128q x 64kv, 256 thr, 8 warps 4wm x 2wn),
// softmax done IN FRAGMENTS (no S smem round trip). exp2-domain.
// ===========================================================================
#define F_QST 68
#define F_KST 68
#define F_VST 72
#define F_SST 68
#define F_QS  0
#define F_KS  (128 * F_QST)
#define F_VS  (F_KS + 64 * F_KST)
#define F_SS  (F_VS + 64 * F_VST)
#define F_MS  (F_SS + 128 * F_SST)
#define F_LS  (F_MS + 128)
#define F_MXP (F_LS + 128)
#define F_LSP (F_MXP + 256)
#define F_SMEM_FLOATS (F_LSP + 256)

__global__ void __launch_bounds__(256, 2) flash_v7_kernel(
    const float* __restrict__ Q, const float* __restrict__ K,
    const float* __restrict__ V, float* __restrict__ O)
{
    extern __shared__ float sm[];
    float* Qs  = sm + F_QS;
    float* Ks  = sm + F_KS;
    float* Vs  = sm + F_VS;
    float* Ss  = sm + F_SS;    // P tile
    float* Ms  = sm + F_MS;    // running row max (exp2 domain)
    float* Ls  = sm + F_LS;    // running row sum
    float* MxP = sm + F_MXP;   // [2][128] per-wn partial max
    float* LsP = sm + F_LSP;   // [2][128] per-wn partial sum

    const int t = threadIdx.x, lane = t & 31, w = t >> 5;
    const int wm = w & 3, wn = w >> 2;
    const int lq = lane >> 2, lc = lane & 3;
    const int bb_ = blockIdx.z, hh = blockIdx.y;
    const int q0 = blockIdx.x * 128;

    const int lr = t >> 4, lcol = (t & 15) * 4;   // Q loader (128 rows, 16 thr/row)
    const int ldr = t >> 2, ldc0 = (t & 3) * 16;  // K/V loader (64 rows, 4 thr/row)

    // stage Q (scaled into exp2 domain + tf32 round)
    {
        const size_t base = ((size_t)bb_ * LQ + q0) * EMBED + hh * DHEAD;
        const float sc = SCALE * LOG2E;
        #pragma unroll
        for (int p = 0; p < 8; p++) {
            int r = p * 16 + lr;
            float4 v = *(const float4*)(Q + base + (size_t)r * EMBED + lcol);
            v.x = tf32r(v.x * sc); v.y = tf32r(v.y * sc);
            v.z = tf32r(v.z * sc); v.w = tf32r(v.w * sc);
            *(float4*)(Qs + r * F_QST + lcol) = v;
        }
    }
    if (t < 128) { Ms[t] = -INFINITY; Ls[t] = 0.f; }

    float4 o[2][4];
    #pragma unroll
    for (int i = 0; i < 2; i++)
        #pragma unroll
        for (int j = 0; j < 4; j++)
            o[i][j] = make_float4(0.f, 0.f, 0.f, 0.f);

    const size_t kvbase = (size_t)bb_ * LK * EMBED + hh * DHEAD;

    for (int kt = 0; kt < LK / 64; kt++) {
        __syncthreads();
        // load K,V tile (64x64 each), tf32-round; 4 threads per row
        {
            size_t g = kvbase + (size_t)(kt * 64 + ldr) * EMBED + ldc0;
            #pragma unroll
            for (int j = 0; j < 4; j++) {
                float4 kv = *(const float4*)(K + g + 4 * j);
                kv.x = tf32r(kv.x); kv.y = tf32r(kv.y);
                kv.z = tf32r(kv.z); kv.w = tf32r(kv.w);
                *(float4*)(Ks + ldr * F_KST + ldc0 + 4 * j) = kv;
            }
            #pragma unroll
            for (int j = 0; j < 4; j++) {
                float4 vv = *(const float4*)(V + g + 4 * j);
                vv.x = tf32r(vv.x); vv.y = tf32r(vv.y);
                vv.z = tf32r(vv.z); vv.w = tf32r(vv.w);
                *(float4*)(Vs + ldr * F_VST + ldc0 + 4 * j) = vv;
            }
        }
        __syncthreads();

        // ---- S = Q @ K^T (scalar frag loads, R2-identical) ----
        float4 s[2][4];
        #pragma unroll
        for (int i = 0; i < 2; i++)
            #pragma unroll
            for (int j = 0; j < 4; j++)
                s[i][j] = make_float4(0.f, 0.f, 0.f, 0.f);

        #pragma unroll
        for (int ks = 0; ks < 8; ks++) {
            float a[2][4];
            #pragma unroll
            for (int mi = 0; mi < 2; mi++) {
                int r = wm * 32 + mi * 16 + lq;
                int c = ks * 8 + lc;
                a[mi][0] = Qs[r * F_QST + c];
                a[mi][1] = Qs[(r + 8) * F_QST + c];
                a[mi][2] = Qs[r * F_QST + c + 4];
                a[mi][3] = Qs[(r + 8) * F_QST + c + 4];
            }
            #pragma unroll
            for (int ni = 0; ni < 4; ni++) {
                int n = wn * 32 + ni * 8 + lq;
                int k = ks * 8 + lc;
                float bfr[2] = { Ks[n * F_KST + k], Ks[n * F_KST + k + 4] };
                #pragma unroll
                for (int mi = 0; mi < 2; mi++)
                    mma_tf32(s[mi][ni], a[mi], bfr);
            }
        }

        // ---- softmax in fragments ----
        // thread owns 4 row-slots: [mi][half] -> row = wm*32+mi*16+lq (+8 if half)
        float mx[2][2];
        #pragma unroll
        for (int mi = 0; mi < 2; mi++) {
            mx[mi][0] = -INFINITY; mx[mi][1] = -INFINITY;
            #pragma unroll
            for (int ni = 0; ni < 4; ni++) {
                mx[mi][0] = fmaxf(mx[mi][0], fmaxf(s[mi][ni].x, s[mi][ni].y));
                mx[mi][1] = fmaxf(mx[mi][1], fmaxf(s[mi][ni].z, s[mi][ni].w));
            }
        }
        #pragma unroll
        for (int mi = 0; mi < 2; mi++)
            #pragma unroll
            for (int h = 0; h < 2; h++) {
                mx[mi][h] = fmaxf(mx[mi][h], __shfl_xor_sync(FULLMASK, mx[mi][h], 1));
                mx[mi][h] = fmaxf(mx[mi][h], __shfl_xor_sync(FULLMASK, mx[mi][h], 2));
            }
        if (lc == 0) {
            #pragma unroll
            for (int mi = 0; mi < 2; mi++) {
                int row = wm * 32 + mi * 16 + lq;
                MxP[wn * 128 + row]     = mx[mi][0];
                MxP[wn * 128 + row + 8] = mx[mi][1];
            }
        }
        __syncthreads();

        float mnew[2][2], corr[2][2], ps[2][2];
        #pragma unroll
        for (int mi = 0; mi < 2; mi++)
            #pragma unroll
            for (int h = 0; h < 2; h++) {
                int row = wm * 32 + mi * 16 + lq + h * 8;
                float ml = fmaxf(MxP[row], MxP[128 + row]);
                float mo = Ms[row];
                mnew[mi][h] = fmaxf(mo, ml);
                corr[mi][h] = exp2f(mo - mnew[mi][h]);
                ps[mi][h] = 0.f;
            }
        #pragma unroll
        for (int mi = 0; mi < 2; mi++) {
            #pragma unroll
            for (int ni = 0; ni < 4; ni++) {
                s[mi][ni].x = exp2f(s[mi][ni].x - mnew[mi][0]); ps[mi][0] += s[mi][ni].x;
                s[mi][ni].y = exp2f(s[mi][ni].y - mnew[mi][0]); ps[mi][0] += s[mi][ni].y;
                s[mi][ni].z = exp2f(s[mi][ni].z - mnew[mi][1]); ps[mi][1] += s[mi][ni].z;
                s[mi][ni].w = exp2f(s[mi][ni].w - mnew[mi][1]); ps[mi][1] += s[mi][ni].w;
            }
        }
        #pragma unroll
        for (int mi = 0; mi < 2; mi++)
            #pragma unroll
            for (int h = 0; h < 2; h++) {
                ps[mi][h] += __shfl_xor_sync(FULLMASK, ps[mi][h], 1);
                ps[mi][h] += __shfl_xor_sync(FULLMASK, ps[mi][h], 2);
            }
        if (lc == 0) {
            #pragma unroll
            for (int mi = 0; mi < 2; mi++) {
                int row = wm * 32 + mi * 16 + lq;
                LsP[wn * 128 + row]     = ps[mi][0];
                LsP[wn * 128 + row + 8] = ps[mi][1];
            }
        }
        // rescale O in registers (corr known per row-slot)
        #pragma unroll
        for (int mi = 0; mi < 2; mi++)
            #pragma unroll
            for (int ni = 0; ni < 4; ni++) {
                o[mi][ni].x *= corr[mi][0]; o[mi][ni].y *= corr[mi][0];
                o[mi][ni].z *= corr[mi][1]; o[mi][ni].w *= corr[mi][1];
            }
        // store P fragments (tf32 rounded)
        #pragma unroll
        for (int mi = 0; mi < 2; mi++) {
            int r = wm * 32 + mi * 16 + lq;
            #pragma unroll
            for (int ni = 0; ni < 4; ni++) {
                int c = wn * 32 + ni * 8 + 2 * lc;
                *(float2*)(Ss + r * F_SST + c) =
                    make_float2(tf32r(s[mi][ni].x), tf32r(s[mi][ni].y));
                *(float2*)(Ss + (r + 8) * F_SST + c) =
                    make_float2(tf32r(s[mi][ni].z), tf32r(s[mi][ni].w));
            }
        }
        __syncthreads();

        // one writer per row updates running stats (wn==0, lc==0)
        if (wn == 0 && lc == 0) {
            #pragma unroll
            for (int mi = 0; mi < 2; mi++)
                #pragma unroll
                for (int h = 0; h < 2; h++) {
                    int row = wm * 32 + mi * 16 + lq + h * 8;
                    Ls[row] = Ls[row] * corr[mi][h] + LsP[row] + LsP[128 + row];
                    Ms[row] = mnew[mi][h];
                }
        }

        // ---- O += P @ V (scalar frag loads, R2-identical) ----
        #pragma unroll
        for (int ks = 0; ks < 8; ks++) {
            float a[2][4];
            #pragma unroll
            for (int mi = 0; mi < 2; mi++) {
                int r = wm * 32 + mi * 16 + lq;
                int c = ks * 8 + lc;
                a[mi][0] = Ss[r * F_SST + c];
                a[mi][1] = Ss[(r + 8) * F_SST + c];
                a[mi][2] = Ss[r * F_SST + c + 4];
                a[mi][3] = Ss[(r + 8) * F_SST + c + 4];
            }
            #pragma unroll
            for (int ni = 0; ni < 4; ni++) {
                int k = ks * 8 + lc;
                int n = wn * 32 + ni * 8 + lq;
                float bfr[2] = { Vs[k * F_VST + n], Vs[(k + 4) * F_VST + n] };
                #pragma unroll
                for (int mi = 0; mi < 2; mi++)
                    mma_tf32(o[mi][ni], a[mi], bfr);
            }
        }
    }

    __syncthreads();
    // epilogue: normalize, write merged-head ctx
    #pragma unroll
    for (int mi = 0; mi < 2; mi++) {
        int r = wm * 32 + mi * 16 + lq;
        float inv0 = 1.f / Ls[r];
        float inv1 = 1.f / Ls[r + 8];
        size_t g0 = ((size_t)bb_ * LQ + q0 + r) * EMBED + hh * DHEAD;
        #pragma unroll
        for (int ni = 0; ni < 4; ni++) {
            int c = wn * 32 + ni * 8 + 2 * lc;
            *(float2*)(O + g0 + c) =
                make_float2(o[mi][ni].x * inv0, o[mi][ni].y * inv0);
            *(float2*)(O + g0 + (size_t)8 * EMBED + c) =
                make_float2(o[mi][ni].z * inv1, o[mi][ni].w * inv1);
        }
    }
}

// ===========================================================================
extern "C" void kernel_launch(void* const* d_in, const int* in_sizes, int n_in,
                              void* d_out, int out_size)
{
    const float* query = (const float*)d_in[0];
    const float* key   = (const float*)d_in[1];
    const float* value = (const float*)d_in[2];
    const float* wq    = (const float*)d_in[3];
    const float* bq    = (const float*)d_in[4];
    const float* wk    = (const float*)d_in[5];
    const float* bk    = (const float*)d_in[6];
    const float* wv    = (const float*)d_in[7];
    const float* bv    = (const float*)d_in[8];
    const float* wo    = (const float*)d_in[9];
    const float* bo    = (const float*)d_in[10];
    float* out = (float*)d_out;

    float *Qp, *Kp, *Vp, *Cp;
    cudaGetSymbolAddress((void**)&Qp, g_Q);
    cudaGetSymbolAddress((void**)&Kp, g_K);
    cudaGetSymbolAddress((void**)&Vp, g_V);
    cudaGetSymbolAddress((void**)&Cp, g_C);

    const size_t gemm_smem  = (size_t)GB_SMEM_U32 * sizeof(uint32_t);
    const size_t flash_smem = (size_t)F_SMEM_FLOATS * sizeof(float);   // ~108.5 KB
    cudaFuncSetAttribute(gemm_bf16x3_kernel,
                         cudaFuncAttributeMaxDynamicSharedMemorySize, (int)gemm_smem);
    cudaFuncSetAttribute(flash_v7_kernel,
                         cudaFuncAttributeMaxDynamicSharedMemorySize, (int)flash_smem);

    dim3 gGemm(EMBED / 128, MROWS / 128);   // (4, 64)

    gemm_bf16x3_kernel<<<gGemm, 256, gemm_smem>>>(query, wq, bq, Qp);
    gemm_bf16x3_kernel<<<gGemm, 256, gemm_smem>>>(key,   wk, bk, Kp);
    gemm_bf16x3_kernel<<<gGemm, 256, gemm_smem>>>(value, wv, bv, Vp);

    flash_v7_kernel<<<dim3(LQ / 128, NHEAD, BATCH), 256, flash_smem>>>(Qp, Kp, Vp, Cp);

    gemm_bf16x3_kernel<<<gGemm, 256, gemm_smem>>>(Cp, wo, bo, out);
}

// round 8
// speedup vs baseline: 1.2545x; 1.0456x over previous
#include <cuda_runtime.h>
#include <cuda_bf16.h>
#include <math.h>
#include <stdint.h>

#define EMBED   512
#define NHEAD   8
#define DHEAD   64
#define LQ      2048
#define LK      2048
#define BATCH   4
#define MROWS   (BATCH * LQ)
#define SCALE   0.125f
#define LOG2E   1.4426950408889634f
#define FULLMASK 0xffffffffu

// ---------------- scratch ----------------
__device__ float g_Q[MROWS * EMBED];
__device__ float g_K[MROWS * EMBED];
__device__ float g_V[MROWS * EMBED];
__device__ float g_C[MROWS * EMBED];

// ---------------- helpers ----------------
__device__ __forceinline__ float tf32r(float x) {
    uint32_t u;
    asm("cvt.rna.tf32.f32 %0, %1;" : "=r"(u) : "f"(x));
    return __uint_as_float(u);
}

__device__ __forceinline__ void ldmx4(uint32_t r[4], uint32_t saddr) {
    asm volatile("ldmatrix.sync.aligned.m8n8.x4.shared.b16 {%0,%1,%2,%3}, [%4];"
                 : "=r"(r[0]), "=r"(r[1]), "=r"(r[2]), "=r"(r[3]) : "r"(saddr));
}

__device__ __forceinline__ void mma_tf32(float4& d, const float* a, const float* b) {
    asm volatile(
        "mma.sync.aligned.m16n8k8.row.col.f32.tf32.tf32.f32 "
        "{%0,%1,%2,%3}, {%4,%5,%6,%7}, {%8,%9}, {%0,%1,%2,%3};"
        : "+f"(d.x), "+f"(d.y), "+f"(d.z), "+f"(d.w)
        : "r"(__float_as_uint(a[0])), "r"(__float_as_uint(a[1])),
          "r"(__float_as_uint(a[2])), "r"(__float_as_uint(a[3])),
          "r"(__float_as_uint(b[0])), "r"(__float_as_uint(b[1])));
}

__device__ __forceinline__ void mma_bf16(float4& d, const uint32_t* a, const uint32_t* b) {
    asm volatile(
        "mma.sync.aligned.m16n8k16.row.col.f32.bf16.bf16.f32 "
        "{%0,%1,%2,%3}, {%4,%5,%6,%7}, {%8,%9}, {%0,%1,%2,%3};"
        : "+f"(d.x), "+f"(d.y), "+f"(d.z), "+f"(d.w)
        : "r"(a[0]), "r"(a[1]), "r"(a[2]), "r"(a[3]), "r"(b[0]), "r"(b[1]));
}

__device__ __forceinline__ uint32_t pack_bf16(float x, float y) {
    __nv_bfloat162 p = __floats2bfloat162_rn(x, y);
    return *reinterpret_cast<uint32_t*>(&p);
}

__device__ __forceinline__ void split_bf16(float v, float& hi_f, float& lo_f) {
    __nv_bfloat16 h = __float2bfloat16_rn(v);
    hi_f = __bfloat162float(h);
    lo_f = v - hi_f;
}

__device__ __forceinline__ void cp16(uint32_t sdst, const void* gsrc) {
    asm volatile("cp.async.cg.shared.global [%0], [%1], 16;"
                 :: "r"(sdst), "l"(gsrc));
}
#define CP_COMMIT() asm volatile("cp.async.commit_group;" ::: "memory")
#define CP_WAIT1()  asm volatile("cp.async.wait_group 1;" ::: "memory")

// ===========================================================================
// GEMM (3x BF16 split) with ldmatrix A-fragments (unchanged, measured ~226us).
// ===========================================================================
#define GB_AST 20
#define GB_WST 136
#define GB_AH  0
#define GB_AL  (128 * GB_AST)
#define GB_WH  (2 * 128 * GB_AST)
#define GB_WL  (2 * 128 * GB_AST + 16 * GB_WST)
#define GB_SMEM_U32 (2 * 128 * GB_AST + 2 * 16 * GB_WST)

__global__ void __launch_bounds__(256, 2) gemm_bf16x3_kernel(
    const float* __restrict__ A, const float* __restrict__ W,
    const float* __restrict__ bias, float* __restrict__ C)
{
    extern __shared__ uint32_t smu[];
    uint32_t* Ah = smu + GB_AH;
    uint32_t* Al = smu + GB_AL;
    uint32_t* Wh = smu + GB_WH;
    uint32_t* Wl = smu + GB_WL;

    const int t = threadIdx.x, lane = t & 31, w = t >> 5;
    const int wm = w & 1, wn = w >> 1;
    const int lq = lane >> 2, lc = lane & 3;
    const int m0 = blockIdx.y * 128, n0 = blockIdx.x * 128;

    const uint32_t sbase = (uint32_t)__cvta_generic_to_shared(smu);

    uint32_t ahp[4], alp[4];
    #pragma unroll
    for (int mi = 0; mi < 4; mi++) {
        int r = wm * 64 + mi * 16 + (lane & 15);
        ahp[mi] = sbase + 4 * (GB_AH + r * GB_AST) + (lane & 16);
        alp[mi] = sbase + 4 * (GB_AL + r * GB_AST) + (lane & 16);
    }

    float4 acc[4][4];
    #pragma unroll
    for (int i = 0; i < 4; i++)
        #pragma unroll
        for (int j = 0; j < 4; j++)
            acc[i][j] = make_float4(0.f, 0.f, 0.f, 0.f);

    const int arow = t >> 1, acol0 = (t & 1) * 16;
    const int wkk  = t >> 4, wcol0 = (t & 15) * 8;

    for (int k0 = 0; k0 < 512; k0 += 32) {
        __syncthreads();
        #pragma unroll
        for (int j = 0; j < 4; j++) {
            float4 v = *(const float4*)(A + (size_t)(m0 + arow) * 512 + k0 + acol0 + 4 * j);
            float hx, lx, hy, ly, hz, lz, hw, lw;
            split_bf16(v.x, hx, lx); split_bf16(v.y, hy, ly);
            split_bf16(v.z, hz, lz); split_bf16(v.w, hw, lw);
            int kk = (acol0 >> 1) + 2 * j;
            *(uint2*)(Ah + arow * GB_AST + kk) = make_uint2(pack_bf16(hx, hy), pack_bf16(hz, hw));
            *(uint2*)(Al + arow * GB_AST + kk) = make_uint2(pack_bf16(lx, ly), pack_bf16(lz, lw));
        }
        #pragma unroll
        for (int j = 0; j < 2; j++) {
            int c = wcol0 + 4 * j;
            float4 va = *(const float4*)(W + (size_t)(k0 + 2 * wkk)     * 512 + n0 + c);
            float4 vb = *(const float4*)(W + (size_t)(k0 + 2 * wkk + 1) * 512 + n0 + c);
            float hax, lax, hay, lay, haz, laz, haw, law;
            float hbx, lbx, hby, lby, hbz, lbz, hbw, lbw;
            split_bf16(va.x, hax, lax); split_bf16(va.y, hay, lay);
            split_bf16(va.z, haz, laz); split_bf16(va.w, haw, law);
            split_bf16(vb.x, hbx, lbx); split_bf16(vb.y, hby, lby);
            split_bf16(vb.z, hbz, lbz); split_bf16(vb.w, hbw, lbw);
            *(uint4*)(Wh + wkk * GB_WST + c) =
                make_uint4(pack_bf16(hax, hbx), pack_bf16(hay, hby),
                           pack_bf16(haz, hbz), pack_bf16(haw, hbw));
            *(uint4*)(Wl + wkk * GB_WST + c) =
                make_uint4(pack_bf16(lax, lbx), pack_bf16(lay, lby),
                           pack_bf16(laz, lbz), pack_bf16(law, lbw));
        }
        __syncthreads();

        #pragma unroll
        for (int ks = 0; ks < 2; ks++) {
            uint32_t bh[4][2], bl[4][2];
            #pragma unroll
            for (int ni = 0; ni < 4; ni++) {
                int n = wn * 32 + ni * 8 + lq;
                bh[ni][0] = Wh[(ks * 8 + lc) * GB_WST + n];
                bh[ni][1] = Wh[(ks * 8 + lc + 4) * GB_WST + n];
                bl[ni][0] = Wl[(ks * 8 + lc) * GB_WST + n];
                bl[ni][1] = Wl[(ks * 8 + lc + 4) * GB_WST + n];
            }
            #pragma unroll
            for (int mi = 0; mi < 4; mi++) {
                uint32_t ah[4], al[4];
                ldmx4(ah, ahp[mi] + ks * 32);
                ldmx4(al, alp[mi] + ks * 32);
                #pragma unroll
                for (int ni = 0; ni < 4; ni++) {
                    mma_bf16(acc[mi][ni], ah, bh[ni]);
                    mma_bf16(acc[mi][ni], ah, bl[ni]);
                    mma_bf16(acc[mi][ni], al, bh[ni]);
                }
            }
        }
    }

    #pragma unroll
    for (int mi = 0; mi < 4; mi++) {
        int r = m0 + wm * 64 + mi * 16 + lq;
        #pragma unroll
        for (int ni = 0; ni < 4; ni++) {
            int c = n0 + wn * 32 + ni * 8 + 2 * lc;
            float b0 = bias[c], b1 = bias[c + 1];
            *(float2*)(C + (size_t)r * 512 + c) =
                make_float2(acc[mi][ni].x + b0, acc[mi][ni].y + b1);
            *(float2*)(C + (size_t)(r + 8) * 512 + c) =
                make_float2(acc[mi][ni].z + b0, acc[mi][ni].w + b1);
        }
    }
}

// ===========================================================================
// Flash attention v8: R7 + cp.async pipelined K/V loads.
// 128q x 64kv, 256 thr, 8 warps (4 wm x 2 wn). Softmax in fragments, exp2.
// K/V stored raw f32 in smem; RNA tf32 rounding applied at fragment load.
// ===========================================================================
#define F_QST 68
#define F_KST 68
#define F_VST 72
#define F_SST 68
#define F_QS  0
#define F_KS  (128 * F_QST)
#define F_VS  (F_KS + 64 * F_KST)
#define F_SS  (F_VS + 64 * F_VST)
#define F_MS  (F_SS + 128 * F_SST)
#define F_LS  (F_MS + 128)
#define F_MXP (F_LS + 128)
#define F_LSP (F_MXP + 256)
#define F_SMEM_FLOATS (F_LSP + 256)
#define NT (LK / 64)

__global__ void __launch_bounds__(256, 2) flash_v8_kernel(
    const float* __restrict__ Q, const float* __restrict__ K,
    const float* __restrict__ V, float* __restrict__ O)
{
    extern __shared__ float sm[];
    float* Qs  = sm + F_QS;
    float* Ks  = sm + F_KS;
    float* Vs  = sm + F_VS;
    float* Ss  = sm + F_SS;
    float* Ms  = sm + F_MS;
    float* Ls  = sm + F_LS;
    float* MxP = sm + F_MXP;
    float* LsP = sm + F_LSP;

    const int t = threadIdx.x, lane = t & 31, w = t >> 5;
    const int wm = w & 3, wn = w >> 2;
    const int lq = lane >> 2, lc = lane & 3;
    const int bb_ = blockIdx.z, hh = blockIdx.y;
    const int q0 = blockIdx.x * 128;

    const uint32_t sbase = (uint32_t)__cvta_generic_to_shared(sm);

    const int lr = t >> 4, lcol = (t & 15) * 4;   // Q loader
    const int ldr = t >> 2, ldc0 = (t & 3) * 16;  // K/V loader (64 rows, 4 thr/row)

    const size_t kvbase = (size_t)bb_ * LK * EMBED + hh * DHEAD;

    // smem dst addresses for this thread's K/V cp.async pieces
    const uint32_t kdst = sbase + 4 * (F_KS + ldr * F_KST + ldc0);
    const uint32_t vdst = sbase + 4 * (F_VS + ldr * F_VST + ldc0);

    // ---- prologue: issue async K(0), V(0) ----
    {
        const float* gk = K + kvbase + (size_t)ldr * EMBED + ldc0;
        const float* gv = V + kvbase + (size_t)ldr * EMBED + ldc0;
        #pragma unroll
        for (int j = 0; j < 4; j++) cp16(kdst + 16 * j, gk + 4 * j);
        CP_COMMIT();
        #pragma unroll
        for (int j = 0; j < 4; j++) cp16(vdst + 16 * j, gv + 4 * j);
        CP_COMMIT();
    }

    // stage Q (scaled into exp2 domain + tf32 round) — overlaps with cp.async
    {
        const size_t base = ((size_t)bb_ * LQ + q0) * EMBED + hh * DHEAD;
        const float sc = SCALE * LOG2E;
        #pragma unroll
        for (int p = 0; p < 8; p++) {
            int r = p * 16 + lr;
            float4 v = *(const float4*)(Q + base + (size_t)r * EMBED + lcol);
            v.x = tf32r(v.x * sc); v.y = tf32r(v.y * sc);
            v.z = tf32r(v.z * sc); v.w = tf32r(v.w * sc);
            *(float4*)(Qs + r * F_QST + lcol) = v;
        }
    }
    if (t < 128) { Ms[t] = -INFINITY; Ls[t] = 0.f; }

    float4 o[2][4];
    #pragma unroll
    for (int i = 0; i < 2; i++)
        #pragma unroll
        for (int j = 0; j < 4; j++)
            o[i][j] = make_float4(0.f, 0.f, 0.f, 0.f);

    for (int kt = 0; kt < NT; kt++) {
        const int ktn = (kt + 1 < NT) ? kt + 1 : kt;   // clamped prefetch tile

        CP_WAIT1();        // K(kt) arrived (V(kt) may still be in flight)
        __syncthreads();   // (a) everyone's K parts + Q (tile 0) visible

        // ---- S = Q @ K^T (round K at fragment load) ----
        float4 s[2][4];
        #pragma unroll
        for (int i = 0; i < 2; i++)
            #pragma unroll
            for (int j = 0; j < 4; j++)
                s[i][j] = make_float4(0.f, 0.f, 0.f, 0.f);

        #pragma unroll
        for (int ks = 0; ks < 8; ks++) {
            float a[2][4];
            #pragma unroll
            for (int mi = 0; mi < 2; mi++) {
                int r = wm * 32 + mi * 16 + lq;
                int c = ks * 8 + lc;
                a[mi][0] = Qs[r * F_QST + c];
                a[mi][1] = Qs[(r + 8) * F_QST + c];
                a[mi][2] = Qs[r * F_QST + c + 4];
                a[mi][3] = Qs[(r + 8) * F_QST + c + 4];
            }
            #pragma unroll
            for (int ni = 0; ni < 4; ni++) {
                int n = wn * 32 + ni * 8 + lq;
                int k = ks * 8 + lc;
                float bfr[2] = { tf32r(Ks[n * F_KST + k]),
                                 tf32r(Ks[n * F_KST + k + 4]) };
                #pragma unroll
                for (int mi = 0; mi < 2; mi++)
                    mma_tf32(s[mi][ni], a[mi], bfr);
            }
        }

        // ---- row max (in fragments) ----
        float mx[2][2];
        #pragma unroll
        for (int mi = 0; mi < 2; mi++) {
            mx[mi][0] = -INFINITY; mx[mi][1] = -INFINITY;
            #pragma unroll
            for (int ni = 0; ni < 4; ni++) {
                mx[mi][0] = fmaxf(mx[mi][0], fmaxf(s[mi][ni].x, s[mi][ni].y));
                mx[mi][1] = fmaxf(mx[mi][1], fmaxf(s[mi][ni].z, s[mi][ni].w));
            }
        }
        #pragma unroll
        for (int mi = 0; mi < 2; mi++)
            #pragma unroll
            for (int h = 0; h < 2; h++) {
                mx[mi][h] = fmaxf(mx[mi][h], __shfl_xor_sync(FULLMASK, mx[mi][h], 1));
                mx[mi][h] = fmaxf(mx[mi][h], __shfl_xor_sync(FULLMASK, mx[mi][h], 2));
            }
        if (lc == 0) {
            #pragma unroll
            for (int mi = 0; mi < 2; mi++) {
                int row = wm * 32 + mi * 16 + lq;
                MxP[wn * 128 + row]     = mx[mi][0];
                MxP[wn * 128 + row + 8] = mx[mi][1];
            }
        }
        __syncthreads();   // (b) MxP visible; all K reads complete CTA-wide

        // ---- issue async K(kt+1) (overwrites Ks — safe after (b)) ----
        {
            const float* gk = K + kvbase + (size_t)(ktn * 64 + ldr) * EMBED + ldc0;
            #pragma unroll
            for (int j = 0; j < 4; j++) cp16(kdst + 16 * j, gk + 4 * j);
            CP_COMMIT();
        }

        float mnew[2][2], corr[2][2], ps[2][2];
        #pragma unroll
        for (int mi = 0; mi < 2; mi++)
            #pragma unroll
            for (int h = 0; h < 2; h++) {
                int row = wm * 32 + mi * 16 + lq + h * 8;
                float ml = fmaxf(MxP[row], MxP[128 + row]);
                float mo = Ms[row];
                mnew[mi][h] = fmaxf(mo, ml);
                corr[mi][h] = exp2f(mo - mnew[mi][h]);
                ps[mi][h] = 0.f;
            }
        #pragma unroll
        for (int mi = 0; mi < 2; mi++) {
            #pragma unroll
            for (int ni = 0; ni < 4; ni++) {
                s[mi][ni].x = exp2f(s[mi][ni].x - mnew[mi][0]); ps[mi][0] += s[mi][ni].x;
                s[mi][ni].y = exp2f(s[mi][ni].y - mnew[mi][0]); ps[mi][0] += s[mi][ni].y;
                s[mi][ni].z = exp2f(s[mi][ni].z - mnew[mi][1]); ps[mi][1] += s[mi][ni].z;
                s[mi][ni].w = exp2f(s[mi][ni].w - mnew[mi][1]); ps[mi][1] += s[mi][ni].w;
            }
        }
        #pragma unroll
        for (int mi = 0; mi < 2; mi++)
            #pragma unroll
            for (int h = 0; h < 2; h++) {
                ps[mi][h] += __shfl_xor_sync(FULLMASK, ps[mi][h], 1);
                ps[mi][h] += __shfl_xor_sync(FULLMASK, ps[mi][h], 2);
            }
        if (lc == 0) {
            #pragma unroll
            for (int mi = 0; mi < 2; mi++) {
                int row = wm * 32 + mi * 16 + lq;
                LsP[wn * 128 + row]     = ps[mi][0];
                LsP[wn * 128 + row + 8] = ps[mi][1];
            }
        }
        // rescale O in registers
        #pragma unroll
        for (int mi = 0; mi < 2; mi++)
            #pragma unroll
            for (int ni = 0; ni < 4; ni++) {
                o[mi][ni].x *= corr[mi][0]; o[mi][ni].y *= corr[mi][0];
                o[mi][ni].z *= corr[mi][1]; o[mi][ni].w *= corr[mi][1];
            }

        CP_WAIT1();        // V(kt) arrived (newest outstanding = K(kt+1))

        // store P fragments (tf32 rounded)
        #pragma unroll
        for (int mi = 0; mi < 2; mi++) {
            int r = wm * 32 + mi * 16 + lq;
            #pragma unroll
            for (int ni = 0; ni < 4; ni++) {
                int c = wn * 32 + ni * 8 + 2 * lc;
                *(float2*)(Ss + r * F_SST + c) =
                    make_float2(tf32r(s[mi][ni].x), tf32r(s[mi][ni].y));
                *(float2*)(Ss + (r + 8) * F_SST + c) =
                    make_float2(tf32r(s[mi][ni].z), tf32r(s[mi][ni].w));
            }
        }
        __syncthreads();   // (c) P + LsP + everyone's V parts visible

        // one writer per row updates running stats
        if (wn == 0 && lc == 0) {
            #pragma unroll
            for (int mi = 0; mi < 2; mi++)
                #pragma unroll
                for (int h = 0; h < 2; h++) {
                    int row = wm * 32 + mi * 16 + lq + h * 8;
                    Ls[row] = Ls[row] * corr[mi][h] + LsP[row] + LsP[128 + row];
                    Ms[row] = mnew[mi][h];
                }
        }

        // ---- O += P @ V (round V at fragment load) ----
        #pragma unroll
        for (int ks = 0; ks < 8; ks++) {
            float a[2][4];
            #pragma unroll
            for (int mi = 0; mi < 2; mi++) {
                int r = wm * 32 + mi * 16 + lq;
                int c = ks * 8 + lc;
                a[mi][0] = Ss[r * F_SST + c];
                a[mi][1] = Ss[(r + 8) * F_SST + c];
                a[mi][2] = Ss[r * F_SST + c + 4];
                a[mi][3] = Ss[(r + 8) * F_SST + c + 4];
            }
            #pragma unroll
            for (int ni = 0; ni < 4; ni++) {
                int k = ks * 8 + lc;
                int n = wn * 32 + ni * 8 + lq;
                float bfr[2] = { tf32r(Vs[k * F_VST + n]),
                                 tf32r(Vs[(k + 4) * F_VST + n]) };
                #pragma unroll
                for (int mi = 0; mi < 2; mi++)
                    mma_tf32(o[mi][ni], a[mi], bfr);
            }
        }
        __syncthreads();   // (d) all V + P reads done; stats written

        // ---- issue async V(kt+1) (overwrites Vs — safe after (d)) ----
        {
            const float* gv = V + kvbase + (size_t)(ktn * 64 + ldr) * EMBED + ldc0;
            #pragma unroll
            for (int j = 0; j < 4; j++) cp16(vdst + 16 * j, gv + 4 * j);
            CP_COMMIT();
        }
    }

    __syncthreads();
    // epilogue: normalize, write merged-head ctx
    #pragma unroll
    for (int mi = 0; mi < 2; mi++) {
        int r = wm * 32 + mi * 16 + lq;
        float inv0 = 1.f / Ls[r];
        float inv1 = 1.f / Ls[r + 8];
        size_t g0 = ((size_t)bb_ * LQ + q0 + r) * EMBED + hh * DHEAD;
        #pragma unroll
        for (int ni = 0; ni < 4; ni++) {
            int c = wn * 32 + ni * 8 + 2 * lc;
            *(float2*)(O + g0 + c) =
                make_float2(o[mi][ni].x * inv0, o[mi][ni].y * inv0);
            *(float2*)(O + g0 + (size_t)8 * EMBED + c) =
                make_float2(o[mi][ni].z * inv1, o[mi][ni].w * inv1);
        }
    }
}

// ===========================================================================
extern "C" void kernel_launch(void* const* d_in, const int* in_sizes, int n_in,
                              void* d_out, int out_size)
{
    const float* query = (const float*)d_in[0];
    const float* key   = (const float*)d_in[1];
    const float* value = (const float*)d_in[2];
    const float* wq    = (const float*)d_in[3];
    const float* bq    = (const float*)d_in[4];
    const float* wk    = (const float*)d_in[5];
    const float* bk    = (const float*)d_in[6];
    const float* wv    = (const float*)d_in[7];
    const float* bv    = (const float*)d_in[8];
    const float* wo    = (const float*)d_in[9];
    const float* bo    = (const float*)d_in[10];
    float* out = (float*)d_out;

    float *Qp, *Kp, *Vp, *Cp;
    cudaGetSymbolAddress((void**)&Qp, g_Q);
    cudaGetSymbolAddress((void**)&Kp, g_K);
    cudaGetSymbolAddress((void**)&Vp, g_V);
    cudaGetSymbolAddress((void**)&Cp, g_C);

    const size_t gemm_smem  = (size_t)GB_SMEM_U32 * sizeof(uint32_t);
    const size_t flash_smem = (size_t)F_SMEM_FLOATS * sizeof(float);
    cudaFuncSetAttribute(gemm_bf16x3_kernel,
                         cudaFuncAttributeMaxDynamicSharedMemorySize, (int)gemm_smem);
    cudaFuncSetAttribute(flash_v8_kernel,
                         cudaFuncAttributeMaxDynamicSharedMemorySize, (int)flash_smem);

    dim3 gGemm(EMBED / 128, MROWS / 128);   // (4, 64)

    gemm_bf16x3_kernel<<<gGemm, 256, gemm_smem>>>(query, wq, bq, Qp);
    gemm_bf16x3_kernel<<<gGemm, 256, gemm_smem>>>(key,   wk, bk, Kp);
    gemm_bf16x3_kernel<<<gGemm, 256, gemm_smem>>>(value, wv, bv, Vp);

    flash_v8_kernel<<<dim3(LQ / 128, NHEAD, BATCH), 256, flash_smem>>>(Qp, Kp, Vp, Cp);

    gemm_bf16x3_kernel<<<gGemm, 256, gemm_smem>>>(Cp, wo, bo, out);
}